// round 3
// baseline (speedup 1.0000x reference)
#include <cuda_runtime.h>
#include <cuda_bf16.h>
#include <cstdint>

#define DEV_INLINE __device__ __forceinline__

// Problem constants
constexpr int Bb = 2, Sq = 2048, Dd = 2048, Hh = 16, DHd = 128;
constexpr int Mrows = Bb * Sq;              // 4096
constexpr float SM_SCALE = 0.08838834764831845f;  // 1/sqrt(128)

// Scratch (device globals -- no allocation allowed)
__device__ float g_Q[(size_t)Mrows * Dd];
__device__ float g_K[(size_t)Mrows * Dd];
__device__ float g_V[(size_t)Mrows * Dd];
__device__ float g_O[(size_t)Mrows * Dd];

DEV_INLINE uint32_t f2tf(float f) {
    uint32_t r;
    asm("cvt.rna.tf32.f32 %0, %1;" : "=r"(r) : "f"(f));
    return r;
}

DEV_INLINE void mma_tf32(float* c, const uint32_t* a, uint32_t b0, uint32_t b1) {
    asm volatile(
        "mma.sync.aligned.m16n8k8.row.col.f32.tf32.tf32.f32 "
        "{%0,%1,%2,%3},{%4,%5,%6,%7},{%8,%9},{%0,%1,%2,%3};"
        : "+f"(c[0]), "+f"(c[1]), "+f"(c[2]), "+f"(c[3])
        : "r"(a[0]), "r"(a[1]), "r"(a[2]), "r"(a[3]), "r"(b0), "r"(b1));
}

// ---------------------------------------------------------------------------
// GEMM: C = A[M,2048] * W[N=2048, K=2048]^T   (row-major A, W rows are output
// features, K contiguous in both -> mma row.col directly).
// MODE 0: Q proj (RoPE + scale, head-major out)
// MODE 1: K proj (RoPE, head-major out)
// MODE 2: V proj (head-major out)
// MODE 3: final  (fp32 [M,N] out)
// ---------------------------------------------------------------------------
template <int MODE>
__global__ __launch_bounds__(256, 2)
void gemm_qkvo(const float* __restrict__ A, const float* __restrict__ W,
               float* __restrict__ C, const float* __restrict__ cosT,
               const float* __restrict__ sinT) {
    constexpr int KDIM = 2048;
    constexpr int LDS = 36;  // 32 + 4 pad: stride%32==4 => conflict-free frags
    __shared__ float As[128 * LDS];
    __shared__ float Ws[128 * LDS];

    const int tid = threadIdx.x;
    const int lane = tid & 31, warp = tid >> 5;
    const int wm = warp >> 2, wn = warp & 3;  // 2 x 4 warp grid
    const int bm = blockIdx.y * 128, bn = blockIdx.x * 128;

    float acc[4][4][4];
#pragma unroll
    for (int i = 0; i < 4; ++i)
#pragma unroll
        for (int j = 0; j < 4; ++j)
#pragma unroll
            for (int e = 0; e < 4; ++e) acc[i][j][e] = 0.f;

    for (int k0 = 0; k0 < KDIM; k0 += 32) {
        __syncthreads();
#pragma unroll
        for (int p = 0; p < 4; ++p) {
            int id = tid + p * 256;      // 1024 chunks of 4 floats
            int r = id >> 3, cc = id & 7;
            float4 va = *(const float4*)&A[(size_t)(bm + r) * KDIM + k0 + cc * 4];
            uint4 ta = {f2tf(va.x), f2tf(va.y), f2tf(va.z), f2tf(va.w)};
            *(uint4*)&As[r * LDS + cc * 4] = ta;
            float4 vb = *(const float4*)&W[(size_t)(bn + r) * KDIM + k0 + cc * 4];
            uint4 tb = {f2tf(vb.x), f2tf(vb.y), f2tf(vb.z), f2tf(vb.w)};
            *(uint4*)&Ws[r * LDS + cc * 4] = tb;
        }
        __syncthreads();

        const uint32_t* Au = (const uint32_t*)As;
        const uint32_t* Wu = (const uint32_t*)Ws;
#pragma unroll
        for (int ks = 0; ks < 4; ++ks) {
            uint32_t af[4][4];
#pragma unroll
            for (int mi = 0; mi < 4; ++mi) {
                int r = wm * 64 + mi * 16 + (lane >> 2);
                int c = ks * 8 + (lane & 3);
                af[mi][0] = Au[r * LDS + c];
                af[mi][1] = Au[(r + 8) * LDS + c];
                af[mi][2] = Au[r * LDS + c + 4];
                af[mi][3] = Au[(r + 8) * LDS + c + 4];
            }
#pragma unroll
            for (int nj = 0; nj < 4; ++nj) {
                int n = wn * 32 + nj * 8 + (lane >> 2);
                int c = ks * 8 + (lane & 3);
                uint32_t b0 = Wu[n * LDS + c];
                uint32_t b1 = Wu[n * LDS + c + 4];
#pragma unroll
                for (int mi = 0; mi < 4; ++mi)
                    mma_tf32(acc[mi][nj], af[mi], b0, b1);
            }
        }
    }

    // Epilogue
#pragma unroll
    for (int mi = 0; mi < 4; ++mi) {
#pragma unroll
        for (int nj = 0; nj < 4; ++nj) {
            int r0 = bm + wm * 64 + mi * 16 + (lane >> 2);
            int c = bn + wn * 32 + nj * 8 + (lane & 3) * 2;
            float v00 = acc[mi][nj][0], v01 = acc[mi][nj][1];
            float v10 = acc[mi][nj][2], v11 = acc[mi][nj][3];
            if (MODE <= 1) {
                int i = (c & 127) >> 1;
                {
                    int s = r0 & (Sq - 1);
                    float cs = cosT[s * 64 + i], sn = sinT[s * 64 + i];
                    float t0 = v00 * cs - v01 * sn;
                    float t1 = v00 * sn + v01 * cs;
                    if (MODE == 0) { t0 *= SM_SCALE; t1 *= SM_SCALE; }
                    v00 = t0; v01 = t1;
                }
                {
                    int s = (r0 + 8) & (Sq - 1);
                    float cs = cosT[s * 64 + i], sn = sinT[s * 64 + i];
                    float t0 = v10 * cs - v11 * sn;
                    float t1 = v10 * sn + v11 * cs;
                    if (MODE == 0) { t0 *= SM_SCALE; t1 *= SM_SCALE; }
                    v10 = t0; v11 = t1;
                }
            }
            if (MODE == 3) {
                float2 lo = {v00, v01}, hi = {v10, v11};
                *(float2*)&C[(size_t)r0 * Dd + c] = lo;
                *(float2*)&C[(size_t)(r0 + 8) * Dd + c] = hi;
            } else {
                int h = c >> 7, d = c & 127;
                int b0i = r0 >> 11, s0 = r0 & (Sq - 1);
                int s1 = (r0 + 8) & (Sq - 1);
                size_t o0 = (((size_t)b0i * Hh + h) * Sq + s0) * DHd + d;
                size_t o1 = (((size_t)b0i * Hh + h) * Sq + s1) * DHd + d;
                float2 lo = {v00, v01}, hi = {v10, v11};
                *(float2*)&C[o0] = lo;
                *(float2*)&C[o1] = hi;
            }
        }
    }
}

// ---------------------------------------------------------------------------
// Flash attention: grid (S/64, B*H), 128 threads (4 warps), each warp owns
// 16 q-rows x full DH=128. Q scaled by 1/sqrt(DH) already.
// smem: Ks[64x132] Vs[64x132] Xs[64x132] (Xs: Q staging, then per-warp P tiles)
// ---------------------------------------------------------------------------
__global__ __launch_bounds__(128)
void attn_kernel(const float* __restrict__ Q, const float* __restrict__ K,
                 const float* __restrict__ V, float* __restrict__ O) {
    extern __shared__ float sm[];
    constexpr int LKV = 132;  // 128 + 4 pad
    constexpr int LP = 68;    // 64 + 4 pad
    float* Ks = sm;
    float* Vs = sm + 64 * LKV;
    float* Xs = sm + 2 * 64 * LKV;

    const int tid = threadIdx.x, lane = tid & 31, warp = tid >> 5;
    const int qt = blockIdx.x, bh = blockIdx.y;
    const size_t base = (size_t)bh * Sq * DHd;

    // Stage Q tile (tf32-rounded) and pull fragments into registers.
    const float* Qg = Q + base + (size_t)qt * 64 * DHd;
    for (int i = tid; i < 64 * 32; i += 128) {
        int r = i >> 5, cc = i & 31;
        float4 v = *(const float4*)&Qg[r * 128 + cc * 4];
        uint4 t = {f2tf(v.x), f2tf(v.y), f2tf(v.z), f2tf(v.w)};
        *(uint4*)&Xs[r * LKV + cc * 4] = t;
    }
    __syncthreads();
    uint32_t qf[16][4];
    {
        const uint32_t* Xu = (const uint32_t*)Xs;
#pragma unroll
        for (int ks = 0; ks < 16; ++ks) {
            int r = warp * 16 + (lane >> 2);
            int c = ks * 8 + (lane & 3);
            qf[ks][0] = Xu[r * LKV + c];
            qf[ks][1] = Xu[(r + 8) * LKV + c];
            qf[ks][2] = Xu[r * LKV + c + 4];
            qf[ks][3] = Xu[(r + 8) * LKV + c + 4];
        }
    }
    __syncthreads();  // Xs now reusable as P tiles

    float oa[16][4];
#pragma unroll
    for (int j = 0; j < 16; ++j)
#pragma unroll
        for (int e = 0; e < 4; ++e) oa[j][e] = 0.f;
    float mrow[2] = {-1e30f, -1e30f}, lrow[2] = {0.f, 0.f};

    uint32_t* Pu = (uint32_t*)(Xs + warp * (16 * LP));

    for (int kt = 0; kt <= qt; ++kt) {
        __syncthreads();  // previous iteration finished with Ks/Vs
        const float* Kg = K + base + (size_t)kt * 64 * DHd;
        const float* Vg = V + base + (size_t)kt * 64 * DHd;
        for (int i = tid; i < 64 * 32; i += 128) {
            int r = i >> 5, cc = i & 31;
            float4 v = *(const float4*)&Kg[r * 128 + cc * 4];
            uint4 t = {f2tf(v.x), f2tf(v.y), f2tf(v.z), f2tf(v.w)};
            *(uint4*)&Ks[r * LKV + cc * 4] = t;
            float4 w = *(const float4*)&Vg[r * 128 + cc * 4];
            uint4 u = {f2tf(w.x), f2tf(w.y), f2tf(w.z), f2tf(w.w)};
            *(uint4*)&Vs[r * LKV + cc * 4] = u;
        }
        __syncthreads();

        // S = Q @ K^T  (16 x 64 per warp)
        float sc[8][4];
#pragma unroll
        for (int j = 0; j < 8; ++j)
#pragma unroll
            for (int e = 0; e < 4; ++e) sc[j][e] = 0.f;
        {
            const uint32_t* Ku = (const uint32_t*)Ks;
#pragma unroll
            for (int ks = 0; ks < 16; ++ks) {
#pragma unroll
                for (int j = 0; j < 8; ++j) {
                    int n = j * 8 + (lane >> 2);
                    int c = ks * 8 + (lane & 3);
                    uint32_t b0 = Ku[n * LKV + c];
                    uint32_t b1 = Ku[n * LKV + c + 4];
                    mma_tf32(sc[j], qf[ks], b0, b1);
                }
            }
        }

        if (kt == qt) {  // diagonal tile: causal mask (local coords equal)
            int rl = warp * 16 + (lane >> 2);
#pragma unroll
            for (int j = 0; j < 8; ++j) {
                int cb = j * 8 + (lane & 3) * 2;
                if (cb > rl) sc[j][0] = -1e30f;
                if (cb + 1 > rl) sc[j][1] = -1e30f;
                if (cb > rl + 8) sc[j][2] = -1e30f;
                if (cb + 1 > rl + 8) sc[j][3] = -1e30f;
            }
        }

        // Online softmax
        float mx0 = -1e30f, mx1 = -1e30f;
#pragma unroll
        for (int j = 0; j < 8; ++j) {
            mx0 = fmaxf(mx0, fmaxf(sc[j][0], sc[j][1]));
            mx1 = fmaxf(mx1, fmaxf(sc[j][2], sc[j][3]));
        }
        mx0 = fmaxf(mx0, __shfl_xor_sync(0xffffffffu, mx0, 1));
        mx0 = fmaxf(mx0, __shfl_xor_sync(0xffffffffu, mx0, 2));
        mx1 = fmaxf(mx1, __shfl_xor_sync(0xffffffffu, mx1, 1));
        mx1 = fmaxf(mx1, __shfl_xor_sync(0xffffffffu, mx1, 2));
        float nm0 = fmaxf(mrow[0], mx0), nm1 = fmaxf(mrow[1], mx1);
        float f0 = __expf(mrow[0] - nm0), f1 = __expf(mrow[1] - nm1);
        float s0 = 0.f, s1 = 0.f;
#pragma unroll
        for (int j = 0; j < 8; ++j) {
            sc[j][0] = __expf(sc[j][0] - nm0);
            sc[j][1] = __expf(sc[j][1] - nm0);
            sc[j][2] = __expf(sc[j][2] - nm1);
            sc[j][3] = __expf(sc[j][3] - nm1);
            s0 += sc[j][0] + sc[j][1];
            s1 += sc[j][2] + sc[j][3];
        }
        s0 += __shfl_xor_sync(0xffffffffu, s0, 1);
        s0 += __shfl_xor_sync(0xffffffffu, s0, 2);
        s1 += __shfl_xor_sync(0xffffffffu, s1, 1);
        s1 += __shfl_xor_sync(0xffffffffu, s1, 2);
        lrow[0] = lrow[0] * f0 + s0;
        lrow[1] = lrow[1] * f1 + s1;
        mrow[0] = nm0;
        mrow[1] = nm1;
#pragma unroll
        for (int j = 0; j < 16; ++j) {
            oa[j][0] *= f0; oa[j][1] *= f0;
            oa[j][2] *= f1; oa[j][3] *= f1;
        }

        // P -> warp-private smem (tf32), then O += P @ V
        __syncwarp();
        {
            int r = lane >> 2, cb = (lane & 3) * 2;
#pragma unroll
            for (int j = 0; j < 8; ++j) {
                Pu[r * LP + j * 8 + cb] = f2tf(sc[j][0]);
                Pu[r * LP + j * 8 + cb + 1] = f2tf(sc[j][1]);
                Pu[(r + 8) * LP + j * 8 + cb] = f2tf(sc[j][2]);
                Pu[(r + 8) * LP + j * 8 + cb + 1] = f2tf(sc[j][3]);
            }
        }
        __syncwarp();
        {
            const uint32_t* Vu = (const uint32_t*)Vs;
#pragma unroll
            for (int ks = 0; ks < 8; ++ks) {
                uint32_t a[4];
                int r = lane >> 2, c = ks * 8 + (lane & 3);
                a[0] = Pu[r * LP + c];
                a[1] = Pu[(r + 8) * LP + c];
                a[2] = Pu[r * LP + c + 4];
                a[3] = Pu[(r + 8) * LP + c + 4];
                int kv = ks * 8 + (lane & 3);
#pragma unroll
                for (int j = 0; j < 16; ++j) {
                    int dcol = j * 8 + (lane >> 2);
                    uint32_t b0 = Vu[kv * LKV + dcol];
                    uint32_t b1 = Vu[(kv + 4) * LKV + dcol];
                    mma_tf32(oa[j], a, b0, b1);
                }
            }
        }
        __syncwarp();
    }

    // Normalize + write O in [B, S, D] layout
    float i0 = 1.f / lrow[0], i1 = 1.f / lrow[1];
    int b = bh >> 4, h = bh & 15;
    int r0 = qt * 64 + warp * 16 + (lane >> 2);
    float* Og = O + ((size_t)b * Sq + r0) * Dd + h * DHd;
#pragma unroll
    for (int j = 0; j < 16; ++j) {
        int dcol = j * 8 + (lane & 3) * 2;
        float2 lo = {oa[j][0] * i0, oa[j][1] * i0};
        float2 hi = {oa[j][2] * i1, oa[j][3] * i1};
        *(float2*)&Og[dcol] = lo;
        *(float2*)&Og[(size_t)8 * Dd + dcol] = hi;
    }
}

// ---------------------------------------------------------------------------
extern "C" void kernel_launch(void* const* d_in, const int* in_sizes, int n_in,
                              void* d_out, int out_size) {
    const float* x = (const float*)d_in[0];
    const float* fc = (const float*)d_in[1];
    const float* fs = (const float*)d_in[2];
    // d_in[3] = mask (unused; causality handled analytically)
    const float* wq = (const float*)d_in[4];
    const float* wk = (const float*)d_in[5];
    const float* wv = (const float*)d_in[6];
    const float* wo = (const float*)d_in[7];
    float* out = (float*)d_out;

    float *Qp, *Kp, *Vp, *Op;
    cudaGetSymbolAddress((void**)&Qp, g_Q);
    cudaGetSymbolAddress((void**)&Kp, g_K);
    cudaGetSymbolAddress((void**)&Vp, g_V);
    cudaGetSymbolAddress((void**)&Op, g_O);

    dim3 gg(Dd / 128, Mrows / 128), gb(256);
    gemm_qkvo<0><<<gg, gb>>>(x, wq, Qp, fc, fs);
    gemm_qkvo<1><<<gg, gb>>>(x, wk, Kp, fc, fs);
    gemm_qkvo<2><<<gg, gb>>>(x, wv, Vp, fc, fs);

    constexpr int ATTN_SMEM = (3 * 64 * 132) * 4;  // 101376 bytes
    cudaFuncSetAttribute(attn_kernel, cudaFuncAttributeMaxDynamicSharedMemorySize,
                         ATTN_SMEM);
    attn_kernel<<<dim3(Sq / 64, Bb * Hh), 128, ATTN_SMEM>>>(Qp, Kp, Vp, Op);

    gemm_qkvo<3><<<gg, gb>>>(Op, wo, out, fc, fs);
}

// round 5
// speedup vs baseline: 1.5592x; 1.5592x over previous
#include <cuda_runtime.h>
#include <cuda_bf16.h>
#include <cstdint>

#define DEV_INLINE __device__ __forceinline__

// Problem constants
constexpr int Bb = 2, Sq = 2048, Dd = 2048, Hh = 16, DHd = 128;
constexpr int Mrows = Bb * Sq;              // 4096
constexpr float SM_SCALE = 0.08838834764831845f;  // 1/sqrt(128)

// Scratch (device globals -- no allocation allowed)
__device__ float g_Q[(size_t)Mrows * Dd];
__device__ float g_K[(size_t)Mrows * Dd];
__device__ float g_V[(size_t)Mrows * Dd];
__device__ float g_O[(size_t)Mrows * Dd];

DEV_INLINE uint32_t f2tf(float f) {
    uint32_t r;
    asm("cvt.rna.tf32.f32 %0, %1;" : "=r"(r) : "f"(f));
    return r;
}

DEV_INLINE void mma_tf32(float* c, const uint32_t* a, uint32_t b0, uint32_t b1) {
    asm volatile(
        "mma.sync.aligned.m16n8k8.row.col.f32.tf32.tf32.f32 "
        "{%0,%1,%2,%3},{%4,%5,%6,%7},{%8,%9},{%0,%1,%2,%3};"
        : "+f"(c[0]), "+f"(c[1]), "+f"(c[2]), "+f"(c[3])
        : "r"(a[0]), "r"(a[1]), "r"(a[2]), "r"(a[3]), "r"(b0), "r"(b1));
}

// ---------------------------------------------------------------------------
// GEMM v2: C = A[M,2048] * W[N,2048]^T, CTA tile 128(M) x 256(N), K-slab 32.
// 256 threads, warp grid 2(m) x 4(n), warp tile 64x64 (mi=4, nj=8).
// Register double-buffering of global loads; tf32 RNA conversion at STS time.
// KIND 0: fused QKV (blockIdx.z selects W/C; modes: 0=Q rope+scale, 1=K rope,
//         2=V plain; head-major [B,H,S,DH] outputs)
// KIND 1: output projection (plain fp32 [M,N] out)
// ---------------------------------------------------------------------------
constexpr int LDSX = 36;  // 32 + 4 pad
constexpr int GEMM_SMEM = (128 * LDSX + 256 * LDSX) * 4;  // 55296 B

template <int KIND>
__global__ __launch_bounds__(256)
void gemm2(const float* __restrict__ A,
           const float* __restrict__ W0, const float* __restrict__ W1,
           const float* __restrict__ W2,
           float* __restrict__ C0, float* __restrict__ C1,
           float* __restrict__ C2,
           const float* __restrict__ cosT, const float* __restrict__ sinT) {
    constexpr int KDIM = 2048;
    extern __shared__ float sm2[];
    float* As = sm2;               // 128 x LDSX
    float* Ws = sm2 + 128 * LDSX;  // 256 x LDSX

    const int tid = threadIdx.x;
    const int lane = tid & 31, warp = tid >> 5;
    const int wm = warp >> 2, wn = warp & 3;  // 2 x 4 warps
    const int bm = blockIdx.y * 128, bn = blockIdx.x * 256;
    const int mode = (KIND == 0) ? (int)blockIdx.z : 3;
    const float* W = (KIND == 0)
                         ? (blockIdx.z == 0 ? W0 : (blockIdx.z == 1 ? W1 : W2))
                         : W0;
    float* C = (KIND == 0)
                   ? (blockIdx.z == 0 ? C0 : (blockIdx.z == 1 ? C1 : C2))
                   : C0;

    // Load indices (fixed per thread)
    const int la_r = tid >> 3, la_c = tid & 7;  // A: 4 chunks, rows +32 apart
    // W: 8 chunks, rows +32 apart

    float acc[4][8][4];
#pragma unroll
    for (int i = 0; i < 4; ++i)
#pragma unroll
        for (int j = 0; j < 8; ++j)
#pragma unroll
            for (int e = 0; e < 4; ++e) acc[i][j][e] = 0.f;

    float4 pa[4], pw[8];
    // Prologue: fetch k-slab 0
#pragma unroll
    for (int p = 0; p < 4; ++p)
        pa[p] = *(const float4*)&A[(size_t)(bm + la_r + p * 32) * KDIM + la_c * 4];
#pragma unroll
    for (int p = 0; p < 8; ++p)
        pw[p] = *(const float4*)&W[(size_t)(bn + la_r + p * 32) * KDIM + la_c * 4];

    for (int k0 = 0; k0 < KDIM; k0 += 32) {
        // Store staged regs -> smem (tf32 RNA at store time)
#pragma unroll
        for (int p = 0; p < 4; ++p) {
            uint4 t = {f2tf(pa[p].x), f2tf(pa[p].y), f2tf(pa[p].z), f2tf(pa[p].w)};
            *(uint4*)&As[(la_r + p * 32) * LDSX + la_c * 4] = t;
        }
#pragma unroll
        for (int p = 0; p < 8; ++p) {
            uint4 t = {f2tf(pw[p].x), f2tf(pw[p].y), f2tf(pw[p].z), f2tf(pw[p].w)};
            *(uint4*)&Ws[(la_r + p * 32) * LDSX + la_c * 4] = t;
        }
        __syncthreads();

        // Prefetch next slab while computing this one
        if (k0 + 32 < KDIM) {
            const int kn = k0 + 32;
#pragma unroll
            for (int p = 0; p < 4; ++p)
                pa[p] = *(const float4*)&A[(size_t)(bm + la_r + p * 32) * KDIM + kn + la_c * 4];
#pragma unroll
            for (int p = 0; p < 8; ++p)
                pw[p] = *(const float4*)&W[(size_t)(bn + la_r + p * 32) * KDIM + kn + la_c * 4];
        }

        const uint32_t* Au = (const uint32_t*)As;
        const uint32_t* Wu = (const uint32_t*)Ws;
#pragma unroll
        for (int ks = 0; ks < 4; ++ks) {
            uint32_t af[4][4];
            const int cfr = ks * 8 + (lane & 3);
#pragma unroll
            for (int mi = 0; mi < 4; ++mi) {
                int r = wm * 64 + mi * 16 + (lane >> 2);
                af[mi][0] = Au[r * LDSX + cfr];
                af[mi][1] = Au[(r + 8) * LDSX + cfr];
                af[mi][2] = Au[r * LDSX + cfr + 4];
                af[mi][3] = Au[(r + 8) * LDSX + cfr + 4];
            }
#pragma unroll
            for (int nj = 0; nj < 8; ++nj) {
                int n = wn * 64 + nj * 8 + (lane >> 2);
                uint32_t b0 = Wu[n * LDSX + cfr];
                uint32_t b1 = Wu[n * LDSX + cfr + 4];
#pragma unroll
                for (int mi = 0; mi < 4; ++mi)
                    mma_tf32(acc[mi][nj], af[mi], b0, b1);
            }
        }
        __syncthreads();
    }

    // Epilogue
#pragma unroll
    for (int mi = 0; mi < 4; ++mi) {
#pragma unroll
        for (int nj = 0; nj < 8; ++nj) {
            int r0 = bm + wm * 64 + mi * 16 + (lane >> 2);
            int c = bn + wn * 64 + nj * 8 + (lane & 3) * 2;
            float v00 = acc[mi][nj][0], v01 = acc[mi][nj][1];
            float v10 = acc[mi][nj][2], v11 = acc[mi][nj][3];
            if (mode <= 1) {
                int i = (c & 127) >> 1;
                {
                    int s = r0 & (Sq - 1);
                    float cs = cosT[s * 64 + i], sn = sinT[s * 64 + i];
                    float t0 = v00 * cs - v01 * sn;
                    float t1 = v00 * sn + v01 * cs;
                    if (mode == 0) { t0 *= SM_SCALE; t1 *= SM_SCALE; }
                    v00 = t0; v01 = t1;
                }
                {
                    int s = (r0 + 8) & (Sq - 1);
                    float cs = cosT[s * 64 + i], sn = sinT[s * 64 + i];
                    float t0 = v10 * cs - v11 * sn;
                    float t1 = v10 * sn + v11 * cs;
                    if (mode == 0) { t0 *= SM_SCALE; t1 *= SM_SCALE; }
                    v10 = t0; v11 = t1;
                }
            }
            if (mode == 3) {
                float2 lo = {v00, v01}, hi = {v10, v11};
                *(float2*)&C[(size_t)r0 * Dd + c] = lo;
                *(float2*)&C[(size_t)(r0 + 8) * Dd + c] = hi;
            } else {
                int h = c >> 7, d = c & 127;
                int b0i = r0 >> 11, s0 = r0 & (Sq - 1);
                int s1 = (r0 + 8) & (Sq - 1);
                size_t o0 = (((size_t)b0i * Hh + h) * Sq + s0) * DHd + d;
                size_t o1 = (((size_t)b0i * Hh + h) * Sq + s1) * DHd + d;
                float2 lo = {v00, v01}, hi = {v10, v11};
                *(float2*)&C[o0] = lo;
                *(float2*)&C[o1] = hi;
            }
        }
    }
}

// ---------------------------------------------------------------------------
// Flash attention: grid (S/64, B*H), 128 threads (4 warps), each warp owns
// 16 q-rows x full DH=128. Q scaled by 1/sqrt(DH) already. (unchanged)
// ---------------------------------------------------------------------------
__global__ __launch_bounds__(128)
void attn_kernel(const float* __restrict__ Q, const float* __restrict__ K,
                 const float* __restrict__ V, float* __restrict__ O) {
    extern __shared__ float sm[];
    constexpr int LKV = 132;  // 128 + 4 pad
    constexpr int LP = 68;    // 64 + 4 pad
    float* Ks = sm;
    float* Vs = sm + 64 * LKV;
    float* Xs = sm + 2 * 64 * LKV;

    const int tid = threadIdx.x, lane = tid & 31, warp = tid >> 5;
    const int qt = blockIdx.x, bh = blockIdx.y;
    const size_t base = (size_t)bh * Sq * DHd;

    // Stage Q tile (tf32-rounded) and pull fragments into registers.
    const float* Qg = Q + base + (size_t)qt * 64 * DHd;
    for (int i = tid; i < 64 * 32; i += 128) {
        int r = i >> 5, cc = i & 31;
        float4 v = *(const float4*)&Qg[r * 128 + cc * 4];
        uint4 t = {f2tf(v.x), f2tf(v.y), f2tf(v.z), f2tf(v.w)};
        *(uint4*)&Xs[r * LKV + cc * 4] = t;
    }
    __syncthreads();
    uint32_t qf[16][4];
    {
        const uint32_t* Xu = (const uint32_t*)Xs;
#pragma unroll
        for (int ks = 0; ks < 16; ++ks) {
            int r = warp * 16 + (lane >> 2);
            int c = ks * 8 + (lane & 3);
            qf[ks][0] = Xu[r * LKV + c];
            qf[ks][1] = Xu[(r + 8) * LKV + c];
            qf[ks][2] = Xu[r * LKV + c + 4];
            qf[ks][3] = Xu[(r + 8) * LKV + c + 4];
        }
    }
    __syncthreads();  // Xs now reusable as P tiles

    float oa[16][4];
#pragma unroll
    for (int j = 0; j < 16; ++j)
#pragma unroll
        for (int e = 0; e < 4; ++e) oa[j][e] = 0.f;
    float mrow[2] = {-1e30f, -1e30f}, lrow[2] = {0.f, 0.f};

    uint32_t* Pu = (uint32_t*)(Xs + warp * (16 * LP));

    for (int kt = 0; kt <= qt; ++kt) {
        __syncthreads();  // previous iteration finished with Ks/Vs
        const float* Kg = K + base + (size_t)kt * 64 * DHd;
        const float* Vg = V + base + (size_t)kt * 64 * DHd;
        for (int i = tid; i < 64 * 32; i += 128) {
            int r = i >> 5, cc = i & 31;
            float4 v = *(const float4*)&Kg[r * 128 + cc * 4];
            uint4 t = {f2tf(v.x), f2tf(v.y), f2tf(v.z), f2tf(v.w)};
            *(uint4*)&Ks[r * LKV + cc * 4] = t;
            float4 w = *(const float4*)&Vg[r * 128 + cc * 4];
            uint4 u = {f2tf(w.x), f2tf(w.y), f2tf(w.z), f2tf(w.w)};
            *(uint4*)&Vs[r * LKV + cc * 4] = u;
        }
        __syncthreads();

        // S = Q @ K^T  (16 x 64 per warp)
        float sc[8][4];
#pragma unroll
        for (int j = 0; j < 8; ++j)
#pragma unroll
            for (int e = 0; e < 4; ++e) sc[j][e] = 0.f;
        {
            const uint32_t* Ku = (const uint32_t*)Ks;
#pragma unroll
            for (int ks = 0; ks < 16; ++ks) {
#pragma unroll
                for (int j = 0; j < 8; ++j) {
                    int n = j * 8 + (lane >> 2);
                    int c = ks * 8 + (lane & 3);
                    uint32_t b0 = Ku[n * LKV + c];
                    uint32_t b1 = Ku[n * LKV + c + 4];
                    mma_tf32(sc[j], qf[ks], b0, b1);
                }
            }
        }

        if (kt == qt) {  // diagonal tile: causal mask (local coords equal)
            int rl = warp * 16 + (lane >> 2);
#pragma unroll
            for (int j = 0; j < 8; ++j) {
                int cb = j * 8 + (lane & 3) * 2;
                if (cb > rl) sc[j][0] = -1e30f;
                if (cb + 1 > rl) sc[j][1] = -1e30f;
                if (cb > rl + 8) sc[j][2] = -1e30f;
                if (cb + 1 > rl + 8) sc[j][3] = -1e30f;
            }
        }

        // Online softmax
        float mx0 = -1e30f, mx1 = -1e30f;
#pragma unroll
        for (int j = 0; j < 8; ++j) {
            mx0 = fmaxf(mx0, fmaxf(sc[j][0], sc[j][1]));
            mx1 = fmaxf(mx1, fmaxf(sc[j][2], sc[j][3]));
        }
        mx0 = fmaxf(mx0, __shfl_xor_sync(0xffffffffu, mx0, 1));
        mx0 = fmaxf(mx0, __shfl_xor_sync(0xffffffffu, mx0, 2));
        mx1 = fmaxf(mx1, __shfl_xor_sync(0xffffffffu, mx1, 1));
        mx1 = fmaxf(mx1, __shfl_xor_sync(0xffffffffu, mx1, 2));
        float nm0 = fmaxf(mrow[0], mx0), nm1 = fmaxf(mrow[1], mx1);
        float f0 = __expf(mrow[0] - nm0), f1 = __expf(mrow[1] - nm1);
        float s0 = 0.f, s1 = 0.f;
#pragma unroll
        for (int j = 0; j < 8; ++j) {
            sc[j][0] = __expf(sc[j][0] - nm0);
            sc[j][1] = __expf(sc[j][1] - nm0);
            sc[j][2] = __expf(sc[j][2] - nm1);
            sc[j][3] = __expf(sc[j][3] - nm1);
            s0 += sc[j][0] + sc[j][1];
            s1 += sc[j][2] + sc[j][3];
        }
        s0 += __shfl_xor_sync(0xffffffffu, s0, 1);
        s0 += __shfl_xor_sync(0xffffffffu, s0, 2);
        s1 += __shfl_xor_sync(0xffffffffu, s1, 1);
        s1 += __shfl_xor_sync(0xffffffffu, s1, 2);
        lrow[0] = lrow[0] * f0 + s0;
        lrow[1] = lrow[1] * f1 + s1;
        mrow[0] = nm0;
        mrow[1] = nm1;
#pragma unroll
        for (int j = 0; j < 16; ++j) {
            oa[j][0] *= f0; oa[j][1] *= f0;
            oa[j][2] *= f1; oa[j][3] *= f1;
        }

        // P -> warp-private smem (tf32), then O += P @ V
        __syncwarp();
        {
            int r = lane >> 2, cb = (lane & 3) * 2;
#pragma unroll
            for (int j = 0; j < 8; ++j) {
                Pu[r * LP + j * 8 + cb] = f2tf(sc[j][0]);
                Pu[r * LP + j * 8 + cb + 1] = f2tf(sc[j][1]);
                Pu[(r + 8) * LP + j * 8 + cb] = f2tf(sc[j][2]);
                Pu[(r + 8) * LP + j * 8 + cb + 1] = f2tf(sc[j][3]);
            }
        }
        __syncwarp();
        {
            const uint32_t* Vu = (const uint32_t*)Vs;
#pragma unroll
            for (int ks = 0; ks < 8; ++ks) {
                uint32_t a[4];
                int r = lane >> 2, c = ks * 8 + (lane & 3);
                a[0] = Pu[r * LP + c];
                a[1] = Pu[(r + 8) * LP + c];
                a[2] = Pu[r * LP + c + 4];
                a[3] = Pu[(r + 8) * LP + c + 4];
                int kv = ks * 8 + (lane & 3);
#pragma unroll
                for (int j = 0; j < 16; ++j) {
                    int dcol = j * 8 + (lane >> 2);
                    uint32_t b0 = Vu[kv * LKV + dcol];
                    uint32_t b1 = Vu[(kv + 4) * LKV + dcol];
                    mma_tf32(oa[j], a, b0, b1);
                }
            }
        }
        __syncwarp();
    }

    // Normalize + write O in [B, S, D] layout
    float i0 = 1.f / lrow[0], i1 = 1.f / lrow[1];
    int b = bh >> 4, h = bh & 15;
    int r0 = qt * 64 + warp * 16 + (lane >> 2);
    float* Og = O + ((size_t)b * Sq + r0) * Dd + h * DHd;
#pragma unroll
    for (int j = 0; j < 16; ++j) {
        int dcol = j * 8 + (lane & 3) * 2;
        float2 lo = {oa[j][0] * i0, oa[j][1] * i0};
        float2 hi = {oa[j][2] * i1, oa[j][3] * i1};
        *(float2*)&Og[dcol] = lo;
        *(float2*)&Og[(size_t)8 * Dd + dcol] = hi;
    }
}

// ---------------------------------------------------------------------------
extern "C" void kernel_launch(void* const* d_in, const int* in_sizes, int n_in,
                              void* d_out, int out_size) {
    const float* x = (const float*)d_in[0];
    const float* fc = (const float*)d_in[1];
    const float* fs = (const float*)d_in[2];
    // d_in[3] = mask (unused; causality handled analytically)
    const float* wq = (const float*)d_in[4];
    const float* wk = (const float*)d_in[5];
    const float* wv = (const float*)d_in[6];
    const float* wo = (const float*)d_in[7];
    float* out = (float*)d_out;

    float *Qp, *Kp, *Vp, *Op;
    cudaGetSymbolAddress((void**)&Qp, g_Q);
    cudaGetSymbolAddress((void**)&Kp, g_K);
    cudaGetSymbolAddress((void**)&Vp, g_V);
    cudaGetSymbolAddress((void**)&Op, g_O);

    cudaFuncSetAttribute(gemm2<0>, cudaFuncAttributeMaxDynamicSharedMemorySize,
                         GEMM_SMEM);
    cudaFuncSetAttribute(gemm2<1>, cudaFuncAttributeMaxDynamicSharedMemorySize,
                         GEMM_SMEM);

    // Fused QKV projections (z = 0:Q, 1:K, 2:V)
    gemm2<0><<<dim3(Dd / 256, Mrows / 128, 3), 256, GEMM_SMEM>>>(
        x, wq, wk, wv, Qp, Kp, Vp, fc, fs);

    constexpr int ATTN_SMEM = (3 * 64 * 132) * 4;  // 101376 bytes
    cudaFuncSetAttribute(attn_kernel, cudaFuncAttributeMaxDynamicSharedMemorySize,
                         ATTN_SMEM);
    attn_kernel<<<dim3(Sq / 64, Bb * Hh), 128, ATTN_SMEM>>>(Qp, Kp, Vp, Op);

    // Output projection
    gemm2<1><<<dim3(Dd / 256, Mrows / 128, 1), 256, GEMM_SMEM>>>(
        Op, wo, nullptr, nullptr, out, nullptr, nullptr, fc, fs);
}